// round 4
// baseline (speedup 1.0000x reference)
#include <cuda_runtime.h>

// MNIST_RNN: 2-layer LSTM (H=10), T=28, D=28, B=32768, + 10-way linear head.
// One thread per batch element; gate pairs accumulated with fma.rn.f32x2.
// R3 root-cause fix: all in-loop shared reads (weights/biases) are
// asm-volatile ld.shared so LICM cannot hoist ~1200 regs of loop-invariant
// weights out of the t-loop (which was forcing a ~736 B/thread local spill).

#define TT 28
#define DD 28
#define HH 10
#define GG 40   // 4*H gates

typedef unsigned long long u64;
typedef unsigned int u32;

__device__ __forceinline__ u32 smem_u32(const void *p) {
    u32 a;
    asm("{ .reg .u64 t; cvta.to.shared.u64 t, %1; cvt.u32.u64 %0, t; }"
        : "=r"(a) : "l"(p));
    return a;
}
__device__ __forceinline__ u64 pack2(float lo, float hi) {
    u64 r;
    asm("mov.b64 %0, {%1, %2};" : "=l"(r) : "f"(lo), "f"(hi));
    return r;
}
__device__ __forceinline__ void unpack2(u64 v, float &lo, float &hi) {
    asm("mov.b64 {%0, %1}, %2;" : "=f"(lo), "=f"(hi) : "l"(v));
}
__device__ __forceinline__ u64 ffma2(u64 a, u64 b, u64 c) {
    u64 d;
    asm("fma.rn.f32x2 %0, %1, %2, %3;" : "=l"(d) : "l"(a), "l"(b), "l"(c));
    return d;
}
// Non-hoistable shared loads (volatile asm = opaque to LICM/CSE).
__device__ __forceinline__ void lds_v2u64(u64 &w0, u64 &w1, u32 addr) {
    asm volatile("ld.shared.v2.u64 {%0, %1}, [%2];"
                 : "=l"(w0), "=l"(w1) : "r"(addr));
}
__device__ __forceinline__ u64 lds_u64(u32 addr) {
    u64 v;
    asm volatile("ld.shared.b64 %0, [%1];" : "=l"(v) : "r"(addr));
    return v;
}

// exp/rcp-based activations (MUFU.EX2 + MUFU.RCP): ~1e-6 abs error.
__device__ __forceinline__ float sigf(float x) {
    return __fdividef(1.0f, 1.0f + __expf(-x));
}
__device__ __forceinline__ float tanhf_(float x) {
    // tanh(x) = 1 - 2/(1 + e^{2x}); e^{2x}=inf -> rcp=0 -> 1. OK.
    return 1.0f - 2.0f * __fdividef(1.0f, 1.0f + __expf(x + x));
}

// a[2q],a[2q+1] (gates 4q..4q+3) += xval * W[row][q]; W row stride 160 B.
#define ACCROW(Wbase, row, xval)                                        \
    {                                                                   \
        u64 _xx = pack2((xval), (xval));                                \
        _Pragma("unroll")                                               \
        for (int q = 0; q < 10; q++) {                                  \
            u64 _w0, _w1;                                               \
            lds_v2u64(_w0, _w1, (Wbase) + ((row) * 10 + q) * 16);       \
            a[2 * q]     = ffma2(_xx, _w0, a[2 * q]);                   \
            a[2 * q + 1] = ffma2(_xx, _w1, a[2 * q + 1]);               \
        }                                                               \
    }

#define ACCROW4(Wbase, base, v4)                                        \
    ACCROW(Wbase, (base) + 0, (v4).x)                                   \
    ACCROW(Wbase, (base) + 1, (v4).y)                                   \
    ACCROW(Wbase, (base) + 2, (v4).z)                                   \
    ACCROW(Wbase, (base) + 3, (v4).w)

#define ACCH(Wbase, hv)                                                 \
    ACCROW(Wbase, 0, hv[0]) ACCROW(Wbase, 1, hv[1])                     \
    ACCROW(Wbase, 2, hv[2]) ACCROW(Wbase, 3, hv[3])                     \
    ACCROW(Wbase, 4, hv[4]) ACCROW(Wbase, 5, hv[5])                     \
    ACCROW(Wbase, 6, hv[6]) ACCROW(Wbase, 7, hv[7])                     \
    ACCROW(Wbase, 8, hv[8]) ACCROW(Wbase, 9, hv[9])

// LSTM pointwise update. For hidden pair (2jj, 2jj+1): i -> a[jj],
// f -> a[5+jj], g -> a[10+jj], o -> a[15+jj]; lane0/1 = hidden 2jj/2jj+1.
#define CELL_UPDATE(hv, cv)                                             \
    {                                                                   \
        _Pragma("unroll")                                               \
        for (int jj = 0; jj < 5; jj++) {                                \
            float i0, i1, f0, f1, g0, g1, o0, o1;                       \
            unpack2(a[jj],      i0, i1);                                \
            unpack2(a[5 + jj],  f0, f1);                                \
            unpack2(a[10 + jj], g0, g1);                                \
            unpack2(a[15 + jj], o0, o1);                                \
            float cn0 = sigf(f0) * cv[2 * jj]     + sigf(i0) * tanhf_(g0); \
            float cn1 = sigf(f1) * cv[2 * jj + 1] + sigf(i1) * tanhf_(g1); \
            cv[2 * jj]     = cn0;                                       \
            cv[2 * jj + 1] = cn1;                                       \
            hv[2 * jj]     = sigf(o0) * tanhf_(cn0);                    \
            hv[2 * jj + 1] = sigf(o1) * tanhf_(cn1);                    \
        }                                                               \
    }

__global__ __launch_bounds__(32)
void mnist_rnn_kernel(const float *__restrict__ x,
                      const float *__restrict__ wih0, const float *__restrict__ whh0,
                      const float *__restrict__ bih0, const float *__restrict__ bhh0,
                      const float *__restrict__ wih1, const float *__restrict__ whh1,
                      const float *__restrict__ bih1, const float *__restrict__ bhh1,
                      const float *__restrict__ wcls, const float *__restrict__ bcls,
                      float *__restrict__ out, int B) {
    // Packed weights: float view index [input*40 + gate] == gate-major pairs.
    __shared__ ulonglong2 sw0x[DD][10];   // w_ih0
    __shared__ ulonglong2 sw0h[HH][10];   // w_hh0
    __shared__ ulonglong2 sw1x[HH][10];   // w_ih1
    __shared__ ulonglong2 sw1h[HH][10];   // w_hh1
    __shared__ u64 sb0[20], sb1[20];      // combined biases, packed pairs
    __shared__ float swc[100], sbc[10];

    const int tid = threadIdx.x;
    for (int i = tid; i < DD * GG; i += 32) {
        int d = i / GG, g = i % GG;
        ((float *)sw0x)[i] = wih0[g * DD + d];
    }
    for (int i = tid; i < HH * GG; i += 32) {
        int j = i / GG, g = i % GG;
        ((float *)sw0h)[i] = whh0[g * HH + j];
        ((float *)sw1x)[i] = wih1[g * HH + j];
        ((float *)sw1h)[i] = whh1[g * HH + j];
    }
    for (int i = tid; i < GG; i += 32) {
        ((float *)sb0)[i] = bih0[i] + bhh0[i];
        ((float *)sb1)[i] = bih1[i] + bhh1[i];
    }
    for (int i = tid; i < 100; i += 32) swc[i] = wcls[i];
    for (int i = tid; i < 10; i += 32) sbc[i] = bcls[i];
    __syncthreads();

    const u32 w0x_b = smem_u32(sw0x);
    const u32 w0h_b = smem_u32(sw0h);
    const u32 w1x_b = smem_u32(sw1x);
    const u32 w1h_b = smem_u32(sw1h);
    const u32 sb0_b = smem_u32(sb0);
    const u32 sb1_b = smem_u32(sb1);

    const int b = blockIdx.x * 32 + tid;
    if (b >= B) return;

    const float *xb = x + (size_t)b * (TT * DD);

    float h0[HH], c0[HH], h1[HH], c1[HH];
#pragma unroll
    for (int j = 0; j < HH; j++) { h0[j] = 0.f; c0[j] = 0.f; h1[j] = 0.f; c1[j] = 0.f; }

#pragma unroll 1
    for (int t = 0; t < TT; t++) {
        // this timestep's x row: 7 x LDG.128 into named float4s (MLP=7)
        const float4 *xr = reinterpret_cast<const float4 *>(xb + t * DD);
        float4 xv0 = xr[0], xv1 = xr[1], xv2 = xr[2], xv3 = xr[3];
        float4 xv4 = xr[4], xv5 = xr[5], xv6 = xr[6];

        u64 a[20];

        // ---- layer 0 ----
#pragma unroll
        for (int p = 0; p < 20; p++) a[p] = lds_u64(sb0_b + p * 8);
        ACCROW4(w0x_b, 0,  xv0)
        ACCROW4(w0x_b, 4,  xv1)
        ACCROW4(w0x_b, 8,  xv2)
        ACCROW4(w0x_b, 12, xv3)
        ACCROW4(w0x_b, 16, xv4)
        ACCROW4(w0x_b, 20, xv5)
        ACCROW4(w0x_b, 24, xv6)
        ACCH(w0h_b, h0)
        CELL_UPDATE(h0, c0)

        // ---- layer 1 ----
#pragma unroll
        for (int p = 0; p < 20; p++) a[p] = lds_u64(sb1_b + p * 8);
        ACCH(w1x_b, h0)
        ACCH(w1h_b, h1)
        CELL_UPDATE(h1, c1)
    }

    // classifier head
#pragma unroll
    for (int k = 0; k < 10; k++) {
        float s = sbc[k];
#pragma unroll
        for (int j = 0; j < HH; j++) s += h1[j] * swc[k * HH + j];
        out[(size_t)b * 10 + k] = s;
    }
}

extern "C" void kernel_launch(void *const *d_in, const int *in_sizes, int n_in,
                              void *d_out, int out_size) {
    const float *x    = (const float *)d_in[0];
    const float *wih0 = (const float *)d_in[1];
    const float *whh0 = (const float *)d_in[2];
    const float *bih0 = (const float *)d_in[3];
    const float *bhh0 = (const float *)d_in[4];
    const float *wih1 = (const float *)d_in[5];
    const float *whh1 = (const float *)d_in[6];
    const float *bih1 = (const float *)d_in[7];
    const float *bhh1 = (const float *)d_in[8];
    const float *wcls = (const float *)d_in[9];
    const float *bcls = (const float *)d_in[10];
    float *out = (float *)d_out;

    const int B = in_sizes[0] / (TT * DD);
    const int block = 32;
    const int grid = (B + block - 1) / block;
    mnist_rnn_kernel<<<grid, block>>>(x, wih0, whh0, bih0, bhh0,
                                      wih1, whh1, bih1, bhh1,
                                      wcls, bcls, out, B);
}